// round 16
// baseline (speedup 1.0000x reference)
#include <cuda_runtime.h>
#include <cuda_fp16.h>
#include <math.h>
#include <stdint.h>

// Problem constants
#define Bb    2
#define NSEQ  2048
#define CDIM  1024
#define HH    8
#define DH    128
#define HALFW 128   // WS/2

// fp16 planes (device globals — no allocation allowed)
__device__ __half g_xh[Bb*NSEQ*CDIM],  g_xl[Bb*NSEQ*CDIM];   // x exact split
__device__ __half g_wqf[3*CDIM*CDIM];                         // w_qkv single
__device__ __half g_wpf[CDIM*CDIM];                           // w_proj single
__device__ __half g_atth[Bb*NSEQ*CDIM], g_attl[Bb*NSEQ*CDIM]; // attn out exact split
// q/k/v single fp16 planes, [B,H,N,D]; q pre-scaled by 1/32
__device__ __half g_qf[Bb*HH*NSEQ*DH];
__device__ __half g_kf[Bb*HH*NSEQ*DH];
__device__ __half g_vf[Bb*HH*NSEQ*DH];

// ================= helpers =================
static __device__ __forceinline__ uint32_t smem_u32(const void* p) {
    uint32_t a;
    asm("{ .reg .u64 t; cvta.to.shared.u64 t, %1; cvt.u32.u64 %0, t; }"
        : "=r"(a) : "l"(p));
    return a;
}
static __device__ __forceinline__ void cp16(uint32_t dst, const void* src) {
    asm volatile("cp.async.cg.shared.global [%0], [%1], 16;"
                 :: "r"(dst), "l"(src));
}
static __device__ __forceinline__ void ldm4(uint32_t* r, uint32_t addr) {
    asm volatile("ldmatrix.sync.aligned.m8n8.x4.shared.b16 {%0,%1,%2,%3}, [%4];"
        : "=r"(r[0]), "=r"(r[1]), "=r"(r[2]), "=r"(r[3]) : "r"(addr));
}
static __device__ __forceinline__ void ldm4t(uint32_t* r, uint32_t addr) {
    asm volatile("ldmatrix.sync.aligned.m8n8.x4.trans.shared.b16 {%0,%1,%2,%3}, [%4];"
        : "=r"(r[0]), "=r"(r[1]), "=r"(r[2]), "=r"(r[3]) : "r"(addr));
}
static __device__ __forceinline__ void mma16816(float* d, const uint32_t* a,
                                                uint32_t b0, uint32_t b1) {
    asm volatile(
        "mma.sync.aligned.m16n8k16.row.col.f32.f16.f16.f32 "
        "{%0,%1,%2,%3}, {%4,%5,%6,%7}, {%8,%9}, {%0,%1,%2,%3};"
        : "+f"(d[0]), "+f"(d[1]), "+f"(d[2]), "+f"(d[3])
        : "r"(a[0]), "r"(a[1]), "r"(a[2]), "r"(a[3]), "r"(b0), "r"(b1));
}
static __device__ __forceinline__ uint32_t pack2h(float a, float b) {
    __half2 t = __floats2half2_rn(a, b);
    return *(uint32_t*)&t;
}
static __device__ __forceinline__ void split2h(float a, float b,
                                               uint32_t& h, uint32_t& l) {
    __half ha = __float2half_rn(a), hb = __float2half_rn(b);
    __half2 H = __halves2half2(ha, hb);
    h = *(uint32_t*)&H;
    l = pack2h(a - __half2float(ha), b - __half2float(hb));
}
static __device__ __forceinline__ float neg_inf() {
    return __int_as_float(0xff800000);
}

// ================= fused pre-pass =================
#define N4X (Bb*NSEQ*CDIM/4)     // 1048576 (hi/lo)
#define N4Q (3*CDIM*CDIM/4)      //  786432 (single)
#define N4P (CDIM*CDIM/4)        //  262144 (single)

__global__ __launch_bounds__(256)
void split_all(const float* __restrict__ x,
               const float* __restrict__ wq,
               const float* __restrict__ wp)
{
    int i = blockIdx.x * 256 + threadIdx.x;
    if (i < N4X) {
        float4 v = ((const float4*)x)[i];
        uint32_t h0, l0, h1, l1;
        split2h(v.x, v.y, h0, l0);
        split2h(v.z, v.w, h1, l1);
        ((uint2*)g_xh)[i] = make_uint2(h0, h1);
        ((uint2*)g_xl)[i] = make_uint2(l0, l1);
    } else if (i < N4X + N4Q) {
        int j = i - N4X;
        float4 v = ((const float4*)wq)[j];
        ((uint2*)g_wqf)[j] = make_uint2(pack2h(v.x, v.y), pack2h(v.z, v.w));
    } else {
        int j = i - N4X - N4Q;
        float4 v = ((const float4*)wp)[j];
        ((uint2*)g_wpf)[j] = make_uint2(pack2h(v.x, v.y), pack2h(v.z, v.w));
    }
}

// ================= fp16 2-term tensor-core GEMM (3-stage cp.async) ========
// C[M,Nout] = (Ah + Al)[M,K] * Bf[Nout,K]^T + bias
// Tile 256x128, 512 threads (16 warps, 4x4 grid, warp tile 64x32)
#define GBM 256
#define GBN 128
#define GKC 32
#define ROWB 80
#define OFF_AH 0
#define OFF_AL 20480
#define OFF_BF 40960
#define STAGEB 51200
#define SM_STG 1024
#define SMEM_GEMM (SM_STG + 3 * STAGEB)   // 154624

template <int MODE>
__global__ __launch_bounds__(512, 1)
void gemm_f16x2(const float* __restrict__ bias,
                float* __restrict__ Cout,
                int K, int Nout)
{
    extern __shared__ char smem[];
    float* sbias = (float*)smem;
    char* stg = smem + SM_STG;
    const uint32_t su = smem_u32(stg);

    const int tid = threadIdx.x;
    const int wid = tid >> 5, lane = tid & 31;
    const int m0 = blockIdx.y * GBM, n0 = blockIdx.x * GBN;
    const int NC = K / GKC;
    const int wm = (wid & 3) * 64;
    const int wn = (wid >> 2) * 32;

    if (tid < GBN) sbias[tid] = bias[n0 + tid];

    const __half* pah = (MODE == 0 ? g_xh  : g_atth) + (size_t)m0 * K;
    const __half* pal = (MODE == 0 ? g_xl  : g_attl) + (size_t)m0 * K;
    const __half* pbf = (MODE == 0 ? g_wqf : g_wpf ) + (size_t)n0 * K;

    const int rA  = tid >> 2;     // 0..127
    const int c16 = tid & 3;

    auto issue = [&](int kc, int s) {
        uint32_t sb = su + s * STAGEB;
#pragma unroll
        for (int hh = 0; hh < 2; hh++) {        // A rows rA, rA+128
            int r = rA + hh * 128;
            size_t go = (size_t)r * K + kc + c16 * 8;
            uint32_t d = (uint32_t)r * ROWB + c16 * 16;
            cp16(sb + OFF_AH + d, pah + go);
            cp16(sb + OFF_AL + d, pal + go);
        }
        {                                        // B row rA
            size_t go = (size_t)rA * K + kc + c16 * 8;
            cp16(sb + OFF_BF + (uint32_t)rA * ROWB + c16 * 16, pbf + go);
        }
        asm volatile("cp.async.commit_group;" ::: "memory");
    };

    float acc[4][4][4];
#pragma unroll
    for (int i = 0; i < 4; i++)
#pragma unroll
        for (int j = 0; j < 4; j++)
#pragma unroll
            for (int q = 0; q < 4; q++) acc[i][j][q] = 0.0f;

    issue(0, 0);
    issue(GKC, 1);

    const uint32_t a_lrow_off = (uint32_t)(wm + (lane & 15)) * ROWB
                              + ((lane >> 4) << 4);
    const uint32_t b_lrow_off = (uint32_t)(wn + ((lane >> 4) << 3) + (lane & 7)) * ROWB
                              + (((lane >> 3) & 1) << 4);

    int s_c = 0;
    for (int c = 0; c < NC; c++) {
        if (c + 1 < NC)
            asm volatile("cp.async.wait_group 1;" ::: "memory");
        else
            asm volatile("cp.async.wait_group 0;" ::: "memory");
        __syncthreads();

        if (c + 2 < NC) {
            int s2 = s_c + 2; if (s2 >= 3) s2 -= 3;
            issue((c + 2) * GKC, s2);
        }

        const uint32_t sb = su + s_c * STAGEB;
#pragma unroll
        for (int ks = 0; ks < 2; ks++) {
            uint32_t ah[4][4], al[4][4];
            uint32_t bh[4][2];
#pragma unroll
            for (int mt = 0; mt < 4; mt++) {
                uint32_t ad = sb + a_lrow_off + (uint32_t)(mt * 16) * ROWB + ks * 32;
                ldm4(ah[mt], ad + OFF_AH);
                ldm4(al[mt], ad + OFF_AL);
            }
#pragma unroll
            for (int p = 0; p < 2; p++) {
                uint32_t t[4];
                ldm4(t, sb + OFF_BF + b_lrow_off + (uint32_t)(p * 16) * ROWB + ks * 32);
                bh[2*p][0] = t[0]; bh[2*p][1] = t[1];
                bh[2*p+1][0] = t[2]; bh[2*p+1][1] = t[3];
            }
#pragma unroll
            for (int mt = 0; mt < 4; mt++)
#pragma unroll
                for (int nt = 0; nt < 4; nt++) {
                    mma16816(acc[mt][nt], ah[mt], bh[nt][0], bh[nt][1]);
                    mma16816(acc[mt][nt], al[mt], bh[nt][0], bh[nt][1]);
                }
        }
        if (++s_c == 3) s_c = 0;
    }

    // epilogue
    const int t  = n0 >> 10;           // MODE 0: q/k/v select
    const int hd = (n0 & 1023) >> 7;
    __half* dst = (t == 0) ? g_qf : ((t == 1) ? g_kf : g_vf);
    const float sc = (t == 0) ? (1.0f / 32.0f) : 1.0f;

#pragma unroll
    for (int mt = 0; mt < 4; mt++) {
#pragma unroll
        for (int nt = 0; nt < 4; nt++) {
            float* d = acc[mt][nt];
            int rr = wm + mt * 16 + (lane >> 2);
            int cc = wn + nt * 8 + (lane & 3) * 2;
            float bb0 = sbias[cc], bb1 = sbias[cc + 1];
            int m1 = m0 + rr, m2 = m1 + 8;
            if (MODE == 0) {
                int b1i = m1 >> 11, nn1 = m1 & 2047;
                size_t o1 = (((size_t)(b1i * HH + hd)) * NSEQ + nn1) * DH + cc;
                *(uint32_t*)&dst[o1] = pack2h((d[0] + bb0) * sc, (d[1] + bb1) * sc);
                int b2i = m2 >> 11, nn2 = m2 & 2047;
                size_t o2 = (((size_t)(b2i * HH + hd)) * NSEQ + nn2) * DH + cc;
                *(uint32_t*)&dst[o2] = pack2h((d[2] + bb0) * sc, (d[3] + bb1) * sc);
            } else {
                float2* p1 = (float2*)(Cout + (size_t)m1 * Nout + n0 + cc);
                *p1 = make_float2(d[0] + bb0, d[1] + bb1);
                float2* p2 = (float2*)(Cout + (size_t)m2 * Nout + n0 + cc);
                *p2 = make_float2(d[2] + bb0, d[3] + bb1);
            }
        }
    }
}

// ================= windowed flash attention — fp16 tensor core ============
// CTA: 64 q-rows, one (b,h); 256 threads = 8 warps.
// QK^T: single fp16 (1 MMA); PV: P hi/lo fp16 x V single (2 MMA).
#define AQ_B  272           // 128 fp16 = 256B + 16 pad
#define AP_B  144           // 64 fp16 = 128B + 16 pad
#define AS_W  68
#define O_QF   0
#define O_KV   17408        // per stage: KF at +0, VF at +17408
#define KV_STG 34816
#define OK_F   0
#define OV_F   17408
#define O_SF   87040
#define O_PH   104448
#define O_PL   113664
#define O_CORR 122880
#define O_LSUM 123136
#define SMEM_ATTN 123392

__global__ __launch_bounds__(256)
void attn_win()
{
    extern __shared__ char smem[];
    const uint32_t su = smem_u32(smem);
    const int tid = threadIdx.x;
    const int lane = tid & 31, wid = tid >> 5;
    const int q0 = blockIdx.x * 64;
    const int bh = blockIdx.y;
    const size_t base = (size_t)bh * NSEQ * DH;
    const float NEGINF = neg_inf();

    // ---- Q tile via cp.async ----
    {
        int row = tid >> 4, ck = tid & 15;
#pragma unroll
        for (int it = 0; it < 4; it++) {
            int r = row + it * 16;
            cp16(su + O_QF + r * AQ_B + ck * 16,
                 g_qf + base + (size_t)(q0 + r) * DH + ck * 8);
        }
        asm volatile("cp.async.commit_group;" ::: "memory");
    }

    int lo = q0 - (HALFW - 1); if (lo < 0) lo = 0;
    int hi = q0 + 63 + (HALFW - 1); if (hi > NSEQ - 1) hi = NSEQ - 1;
    const int kt0 = lo & ~63;
    const int ntiles = ((hi - kt0) >> 6) + 1;

    auto load_kv = [&](int t, int s) {
        int kt = kt0 + t * 64;
        uint32_t sb = su + O_KV + s * KV_STG;
        int row = tid >> 4, ck = tid & 15;
#pragma unroll
        for (int it = 0; it < 4; it++) {
            int r = row + it * 16;
            size_t go = base + (size_t)(kt + r) * DH + ck * 8;
            uint32_t d = r * AQ_B + ck * 16;
            cp16(sb + OK_F + d, g_kf + go);
            cp16(sb + OV_F + d, g_vf + go);
        }
        asm volatile("cp.async.commit_group;" ::: "memory");
    };
    load_kv(0, 0);

    const int wq = wid >> 1;
    const int wk = wid & 1;
    const uint32_t aq_off = (uint32_t)(wq * 16 + (lane & 15)) * AQ_B
                          + ((lane >> 4) << 4);
    const uint32_t bk_off = (uint32_t)(wk * 32 + ((lane >> 4) << 3) + (lane & 7)) * AQ_B
                          + (((lane >> 3) & 1) << 4);
    const uint32_t ap_off = (uint32_t)(wq * 16 + (lane & 15)) * AP_B
                          + ((lane >> 4) << 4);
    const uint32_t bv_row = (lane & 7) + ((lane >> 3) & 1) * 8;
    const uint32_t bv_c16 = ((lane >> 4) << 4);

    const int tx = tid & 15, ty = tid >> 4;
    float mrow[4], lsum[4];
#pragma unroll
    for (int i = 0; i < 4; i++) { mrow[i] = NEGINF; lsum[i] = 0.0f; }

    float oacc[4][2][4];
#pragma unroll
    for (int a = 0; a < 4; a++)
#pragma unroll
        for (int b = 0; b < 2; b++)
#pragma unroll
            for (int q = 0; q < 4; q++) oacc[a][b][q] = 0.0f;

    float* Sf = (float*)(smem + O_SF);
    float* scorr = (float*)(smem + O_CORR);
    float* slsum = (float*)(smem + O_LSUM);

    for (int t = 0; t < ntiles; t++) {
        const int s = t & 1;
        const uint32_t kvb = su + O_KV + s * KV_STG;

        __syncthreads();
        if (t + 1 < ntiles) {
            load_kv(t + 1, s ^ 1);
            asm volatile("cp.async.wait_group 1;" ::: "memory");
        } else {
            asm volatile("cp.async.wait_group 0;" ::: "memory");
        }
        __syncthreads();

        // ---- phase A: S = Q K^T (single fp16) ----
        float sacc[4][4];
#pragma unroll
        for (int nt = 0; nt < 4; nt++)
#pragma unroll
            for (int q = 0; q < 4; q++) sacc[nt][q] = 0.0f;

#pragma unroll
        for (int ks = 0; ks < 8; ks++) {
            uint32_t ah[4];
            ldm4(ah, su + O_QF + aq_off + ks * 32);
            uint32_t bh[4][2];
#pragma unroll
            for (int p = 0; p < 2; p++) {
                uint32_t tt[4];
                ldm4(tt, kvb + OK_F + bk_off + (uint32_t)(p * 16) * AQ_B + ks * 32);
                bh[2*p][0] = tt[0]; bh[2*p][1] = tt[1];
                bh[2*p+1][0] = tt[2]; bh[2*p+1][1] = tt[3];
            }
#pragma unroll
            for (int nt = 0; nt < 4; nt++)
                mma16816(sacc[nt], ah, bh[nt][0], bh[nt][1]);
        }
        {
            int r1 = wq * 16 + (lane >> 2);
            int cb = wk * 32 + (lane & 3) * 2;
#pragma unroll
            for (int nt = 0; nt < 4; nt++) {
                float* p1 = Sf + r1 * AS_W + cb + nt * 8;
                p1[0] = sacc[nt][0]; p1[1] = sacc[nt][1];
                float* p2 = p1 + 8 * AS_W;
                p2[0] = sacc[nt][2]; p2[1] = sacc[nt][3];
            }
        }
        __syncthreads();

        // ---- phase B: online softmax, P -> fp16 hi/lo planes ----
        const int kt = kt0 + t * 64;
#pragma unroll
        for (int i = 0; i < 4; i++) {
            int row = ty * 4 + i;
            int qg = q0 + row;
            float4 sv = *(float4*)(Sf + row * AS_W + tx * 4);
            float sA[4] = {sv.x, sv.y, sv.z, sv.w};
#pragma unroll
            for (int j = 0; j < 4; j++) {
                int jg = kt + tx * 4 + j;
                int d = qg - jg; if (d < 0) d = -d;
                if (d >= HALFW) sA[j] = NEGINF;
            }
            float rm = fmaxf(fmaxf(sA[0], sA[1]), fmaxf(sA[2], sA[3]));
            rm = fmaxf(rm, __shfl_xor_sync(0xffffffffu, rm, 1));
            rm = fmaxf(rm, __shfl_xor_sync(0xffffffffu, rm, 2));
            rm = fmaxf(rm, __shfl_xor_sync(0xffffffffu, rm, 4));
            rm = fmaxf(rm, __shfl_xor_sync(0xffffffffu, rm, 8));
            float mnew = fmaxf(mrow[i], rm);
            float corr, p[4];
            if (mnew == NEGINF) {
                corr = 1.0f;
                p[0] = p[1] = p[2] = p[3] = 0.0f;
            } else {
                corr = __expf(mrow[i] - mnew);
#pragma unroll
                for (int j = 0; j < 4; j++) p[j] = __expf(sA[j] - mnew);
            }
            float rs = (p[0] + p[1]) + (p[2] + p[3]);
            rs += __shfl_xor_sync(0xffffffffu, rs, 1);
            rs += __shfl_xor_sync(0xffffffffu, rs, 2);
            rs += __shfl_xor_sync(0xffffffffu, rs, 4);
            rs += __shfl_xor_sync(0xffffffffu, rs, 8);
            lsum[i] = lsum[i] * corr + rs;
            mrow[i] = mnew;
            uint32_t h01, l01, h23, l23;
            split2h(p[0], p[1], h01, l01);
            split2h(p[2], p[3], h23, l23);
            *(uint2*)((char*)smem + O_PH + row * AP_B + tx * 8) = make_uint2(h01, h23);
            *(uint2*)((char*)smem + O_PL + row * AP_B + tx * 8) = make_uint2(l01, l23);
            if (tx == 0) scorr[row] = corr;
        }
        __syncthreads();

        // ---- phase C: O = corr*O + (Ph+Pl) V ----
        {
            int r1 = wq * 16 + (lane >> 2);
            float c1 = scorr[r1], c2 = scorr[r1 + 8];
#pragma unroll
            for (int a = 0; a < 4; a++)
#pragma unroll
                for (int b = 0; b < 2; b++) {
                    oacc[a][b][0] *= c1; oacc[a][b][1] *= c1;
                    oacc[a][b][2] *= c2; oacc[a][b][3] *= c2;
                }
#pragma unroll
            for (int kk = 0; kk < 4; kk++) {
                uint32_t ph[4], pl[4];
                ldm4(ph, su + O_PH + ap_off + kk * 32);
                ldm4(pl, su + O_PL + ap_off + kk * 32);
#pragma unroll
                for (int t16 = 0; t16 < 4; t16++) {
                    uint32_t va = kvb + OV_F + (uint32_t)(kk * 16 + bv_row) * AQ_B
                                + (uint32_t)(wk * 64 + t16 * 16) * 2 + bv_c16;
                    uint32_t vf[4];
                    ldm4t(vf, va);
                    mma16816(oacc[t16][0], ph, vf[0], vf[1]);
                    mma16816(oacc[t16][0], pl, vf[0], vf[1]);
                    mma16816(oacc[t16][1], ph, vf[2], vf[3]);
                    mma16816(oacc[t16][1], pl, vf[2], vf[3]);
                }
            }
        }
    }

    // ---- epilogue: normalize, write att fp16 hi/lo planes ----
#pragma unroll
    for (int i = 0; i < 4; i++)
        if (tx == 0) slsum[ty * 4 + i] = lsum[i];
    __syncthreads();
    {
        int r1 = wq * 16 + (lane >> 2), r2 = r1 + 8;
        float inv1 = 1.0f / slsum[r1];
        float inv2 = 1.0f / slsum[r2];
        const int b = bh >> 3, h = bh & 7;
        size_t ob1 = ((size_t)b * NSEQ + (q0 + r1)) * CDIM + h * DH;
        size_t ob2 = ((size_t)b * NSEQ + (q0 + r2)) * CDIM + h * DH;
#pragma unroll
        for (int t16 = 0; t16 < 4; t16++)
#pragma unroll
            for (int hf = 0; hf < 2; hf++) {
                int c = wk * 64 + t16 * 16 + hf * 8 + (lane & 3) * 2;
                float* d = oacc[t16][hf];
                uint32_t hh, ll;
                split2h(d[0] * inv1, d[1] * inv1, hh, ll);
                *(uint32_t*)&g_atth[ob1 + c] = hh;
                *(uint32_t*)&g_attl[ob1 + c] = ll;
                split2h(d[2] * inv2, d[3] * inv2, hh, ll);
                *(uint32_t*)&g_atth[ob2 + c] = hh;
                *(uint32_t*)&g_attl[ob2 + c] = ll;
            }
    }
}

// ---------------- launch ----------------
extern "C" void kernel_launch(void* const* d_in, const int* in_sizes, int n_in,
                              void* d_out, int out_size)
{
    const float* x      = (const float*)d_in[0];
    const float* w_qkv  = (const float*)d_in[1];
    const float* b_qkv  = (const float*)d_in[2];
    const float* w_proj = (const float*)d_in[3];
    const float* b_proj = (const float*)d_in[4];
    float* out = (float*)d_out;

    cudaFuncSetAttribute(gemm_f16x2<0>,
                         cudaFuncAttributeMaxDynamicSharedMemorySize, SMEM_GEMM);
    cudaFuncSetAttribute(gemm_f16x2<1>,
                         cudaFuncAttributeMaxDynamicSharedMemorySize, SMEM_GEMM);
    cudaFuncSetAttribute(attn_win,
                         cudaFuncAttributeMaxDynamicSharedMemorySize, SMEM_ATTN);

    // 0) split/convert all inputs to fp16 planes (one fused launch)
    split_all<<<(N4X + N4Q + N4P) / 256, 256>>>(x, w_qkv, w_proj);

    // 1) QKV projection -> q/k/v single fp16 planes [B,H,N,D] (q pre-scaled)
    dim3 g1((3 * CDIM) / GBN, (Bb * NSEQ) / GBM);   // (24, 16)
    gemm_f16x2<0><<<g1, 512, SMEM_GEMM>>>(b_qkv, nullptr, CDIM, 3 * CDIM);

    // 2) banded attention (fp16 tensor core) -> g_atth/g_attl planes
    dim3 g2(NSEQ / 64, Bb * HH);                    // (32, 16)
    attn_win<<<g2, 256, SMEM_ATTN>>>();

    // 3) output projection
    dim3 g3(CDIM / GBN, (Bb * NSEQ) / GBM);         // (8, 16)
    gemm_f16x2<1><<<g3, 512, SMEM_GEMM>>>(b_proj, out, CDIM, CDIM);
}

// round 17
// speedup vs baseline: 1.1087x; 1.1087x over previous
#include <cuda_runtime.h>
#include <cuda_bf16.h>
#include <math.h>
#include <stdint.h>

// Problem constants
#define Bb    2
#define NSEQ  2048
#define CDIM  1024
#define HH    8
#define DH    128
#define HALFW 128   // WS/2

// bf16 hi/lo planes (device globals — no allocation allowed)
__device__ __nv_bfloat16 g_xh[Bb*NSEQ*CDIM],  g_xl[Bb*NSEQ*CDIM];
__device__ __nv_bfloat16 g_wqh[3*CDIM*CDIM],  g_wql[3*CDIM*CDIM];
__device__ __nv_bfloat16 g_wph[CDIM*CDIM],    g_wpl[CDIM*CDIM];
__device__ __nv_bfloat16 g_atth[Bb*NSEQ*CDIM], g_attl[Bb*NSEQ*CDIM];
// q/k/v planes, [B,H,N,D]; q pre-scaled by 1/32
__device__ __nv_bfloat16 g_qh[Bb*HH*NSEQ*DH], g_ql[Bb*HH*NSEQ*DH];
__device__ __nv_bfloat16 g_kh[Bb*HH*NSEQ*DH], g_kl[Bb*HH*NSEQ*DH];
__device__ __nv_bfloat16 g_vh[Bb*HH*NSEQ*DH], g_vl[Bb*HH*NSEQ*DH];

// ================= helpers =================
static __device__ __forceinline__ uint32_t smem_u32(const void* p) {
    uint32_t a;
    asm("{ .reg .u64 t; cvta.to.shared.u64 t, %1; cvt.u32.u64 %0, t; }"
        : "=r"(a) : "l"(p));
    return a;
}
static __device__ __forceinline__ void cp16(uint32_t dst, const void* src) {
    asm volatile("cp.async.cg.shared.global [%0], [%1], 16;"
                 :: "r"(dst), "l"(src));
}
static __device__ __forceinline__ void ldm4(uint32_t* r, uint32_t addr) {
    asm volatile("ldmatrix.sync.aligned.m8n8.x4.shared.b16 {%0,%1,%2,%3}, [%4];"
        : "=r"(r[0]), "=r"(r[1]), "=r"(r[2]), "=r"(r[3]) : "r"(addr));
}
static __device__ __forceinline__ void ldm4t(uint32_t* r, uint32_t addr) {
    asm volatile("ldmatrix.sync.aligned.m8n8.x4.trans.shared.b16 {%0,%1,%2,%3}, [%4];"
        : "=r"(r[0]), "=r"(r[1]), "=r"(r[2]), "=r"(r[3]) : "r"(addr));
}
static __device__ __forceinline__ void mma16816(float* d, const uint32_t* a,
                                                uint32_t b0, uint32_t b1) {
    asm volatile(
        "mma.sync.aligned.m16n8k16.row.col.f32.bf16.bf16.f32 "
        "{%0,%1,%2,%3}, {%4,%5,%6,%7}, {%8,%9}, {%0,%1,%2,%3};"
        : "+f"(d[0]), "+f"(d[1]), "+f"(d[2]), "+f"(d[3])
        : "r"(a[0]), "r"(a[1]), "r"(a[2]), "r"(a[3]), "r"(b0), "r"(b1));
}
static __device__ __forceinline__ uint32_t pack2(__nv_bfloat16 a, __nv_bfloat16 b) {
    __nv_bfloat162 t(a, b);
    return *(uint32_t*)&t;
}
static __device__ __forceinline__ void split2(float a, float b,
                                              uint32_t& h, uint32_t& l) {
    __nv_bfloat16 ha = __float2bfloat16(a), hb = __float2bfloat16(b);
    h = pack2(ha, hb);
    l = pack2(__float2bfloat16(a - __bfloat162float(ha)),
              __float2bfloat16(b - __bfloat162float(hb)));
}
static __device__ __forceinline__ void split4(float4 v, uint2& hi, uint2& lo) {
    split2(v.x, v.y, hi.x, lo.x);
    split2(v.z, v.w, hi.y, lo.y);
}
static __device__ __forceinline__ float neg_inf() {
    return __int_as_float(0xff800000);
}

// ================= fused pre-pass: split all inputs into hi/lo planes ======
#define N4X (Bb*NSEQ*CDIM/4)     // 1048576
#define N4Q (3*CDIM*CDIM/4)      //  786432
#define N4P (CDIM*CDIM/4)        //  262144

__global__ __launch_bounds__(256)
void split_all(const float* __restrict__ x,
               const float* __restrict__ wq,
               const float* __restrict__ wp)
{
    int i = blockIdx.x * 256 + threadIdx.x;
    const float* src;
    __nv_bfloat16 *h, *l;
    int j;
    if (i < N4X) {
        src = x; h = g_xh; l = g_xl; j = i;
    } else if (i < N4X + N4Q) {
        src = wq; h = g_wqh; l = g_wql; j = i - N4X;
    } else {
        src = wp; h = g_wph; l = g_wpl; j = i - N4X - N4Q;
    }
    float4 v = ((const float4*)src)[j];
    uint2 hh, ll;
    split4(v, hh, ll);
    ((uint2*)h)[j] = hh;
    ((uint2*)l)[j] = ll;
}

// ================= bf16x3 tensor-core GEMM — 3-stage cp.async =============
// C[M,Nout] = A[M,K] * B[Nout,K]^T + bias
// Tile 256x128, 512 threads (16 warps, 4x4 warp grid, warp tile 64x32)
// MMA issue is TERM-MAJOR: same-accumulator reuse distance = 16 instructions.
#define GBM 256
#define GBN 128
#define GKC 32
#define ROWB 80
#define OFF_AH 0
#define OFF_AL 20480
#define OFF_BH 40960
#define OFF_BL 51200
#define STAGEB 61440
#define SM_STG 1024
#define SMEM_GEMM (SM_STG + 3 * STAGEB)   // 185344

template <int MODE>
__global__ __launch_bounds__(512, 1)
void gemm_bf16x3(const float* __restrict__ bias,
                 float* __restrict__ Cout,
                 int K, int Nout)
{
    extern __shared__ char smem[];
    float* sbias = (float*)smem;
    char* stg = smem + SM_STG;
    const uint32_t su = smem_u32(stg);

    const int tid = threadIdx.x;
    const int wid = tid >> 5, lane = tid & 31;
    const int m0 = blockIdx.y * GBM, n0 = blockIdx.x * GBN;
    const int NC = K / GKC;
    const int wm = (wid & 3) * 64;
    const int wn = (wid >> 2) * 32;

    if (tid < GBN) sbias[tid] = bias[n0 + tid];

    const __nv_bfloat16* pb[4];
    if (MODE == 0) {
        pb[0] = g_xh  + (size_t)m0 * K;
        pb[1] = g_xl  + (size_t)m0 * K;
        pb[2] = g_wqh + (size_t)n0 * K;
        pb[3] = g_wql + (size_t)n0 * K;
    } else {
        pb[0] = g_atth + (size_t)m0 * K;
        pb[1] = g_attl + (size_t)m0 * K;
        pb[2] = g_wph  + (size_t)n0 * K;
        pb[3] = g_wpl  + (size_t)n0 * K;
    }

    const int rA  = tid >> 2;     // 0..127
    const int c16 = tid & 3;

    auto issue = [&](int kc, int s) {
        uint32_t sb = su + s * STAGEB;
#pragma unroll
        for (int hh = 0; hh < 2; hh++) {        // A rows rA, rA+128
            int r = rA + hh * 128;
            size_t go = (size_t)r * K + kc + c16 * 8;
            uint32_t d = (uint32_t)r * ROWB + c16 * 16;
            cp16(sb + OFF_AH + d, pb[0] + go);
            cp16(sb + OFF_AL + d, pb[1] + go);
        }
        {                                        // B row rA
            size_t go = (size_t)rA * K + kc + c16 * 8;
            uint32_t d = (uint32_t)rA * ROWB + c16 * 16;
            cp16(sb + OFF_BH + d, pb[2] + go);
            cp16(sb + OFF_BL + d, pb[3] + go);
        }
        asm volatile("cp.async.commit_group;" ::: "memory");
    };

    float acc[4][4][4];
#pragma unroll
    for (int i = 0; i < 4; i++)
#pragma unroll
        for (int j = 0; j < 4; j++)
#pragma unroll
            for (int q = 0; q < 4; q++) acc[i][j][q] = 0.0f;

    issue(0, 0);
    issue(GKC, 1);

    const uint32_t a_lrow_off = (uint32_t)(wm + (lane & 15)) * ROWB
                              + ((lane >> 4) << 4);
    const uint32_t b_lrow_off = (uint32_t)(wn + ((lane >> 4) << 3) + (lane & 7)) * ROWB
                              + (((lane >> 3) & 1) << 4);

    int s_c = 0;
    for (int c = 0; c < NC; c++) {
        if (c + 1 < NC)
            asm volatile("cp.async.wait_group 1;" ::: "memory");
        else
            asm volatile("cp.async.wait_group 0;" ::: "memory");
        __syncthreads();

        if (c + 2 < NC) {
            int s2 = s_c + 2; if (s2 >= 3) s2 -= 3;
            issue((c + 2) * GKC, s2);
        }

        const uint32_t sb = su + s_c * STAGEB;
#pragma unroll
        for (int ks = 0; ks < 2; ks++) {
            uint32_t ah[4][4], al[4][4];
            uint32_t bh[4][2], bl[4][2];
#pragma unroll
            for (int mt = 0; mt < 4; mt++) {
                uint32_t ad = sb + a_lrow_off + (uint32_t)(mt * 16) * ROWB + ks * 32;
                ldm4(ah[mt], ad + OFF_AH);
                ldm4(al[mt], ad + OFF_AL);
            }
#pragma unroll
            for (int p = 0; p < 2; p++) {
                uint32_t bd = sb + b_lrow_off + (uint32_t)(p * 16) * ROWB + ks * 32;
                uint32_t t[4];
                ldm4(t, bd + OFF_BH);
                bh[2*p][0] = t[0]; bh[2*p][1] = t[1];
                bh[2*p+1][0] = t[2]; bh[2*p+1][1] = t[3];
                ldm4(t, bd + OFF_BL);
                bl[2*p][0] = t[0]; bl[2*p][1] = t[1];
                bl[2*p+1][0] = t[2]; bl[2*p+1][1] = t[3];
            }
            // term-major issue: each accumulator revisited every 16 MMAs
#pragma unroll
            for (int term = 0; term < 3; term++) {
#pragma unroll
                for (int mt = 0; mt < 4; mt++) {
                    const uint32_t* aa = (term == 2) ? al[mt] : ah[mt];
#pragma unroll
                    for (int nt = 0; nt < 4; nt++) {
                        const uint32_t* bb = (term == 1) ? bl[nt] : bh[nt];
                        mma16816(acc[mt][nt], aa, bb[0], bb[1]);
                    }
                }
            }
        }
        if (++s_c == 3) s_c = 0;
    }

    // epilogue
    const int t  = n0 >> 10;           // MODE 0: q/k/v select (GBN=128)
    const int hd = (n0 & 1023) >> 7;
    __nv_bfloat16* dh = (t == 0) ? g_qh : ((t == 1) ? g_kh : g_vh);
    __nv_bfloat16* dl = (t == 0) ? g_ql : ((t == 1) ? g_kl : g_vl);
    const float sc = (t == 0) ? (1.0f / 32.0f) : 1.0f;

#pragma unroll
    for (int mt = 0; mt < 4; mt++) {
#pragma unroll
        for (int nt = 0; nt < 4; nt++) {
            float* d = acc[mt][nt];
            int rr = wm + mt * 16 + (lane >> 2);
            int cc = wn + nt * 8 + (lane & 3) * 2;
            float bb0 = sbias[cc], bb1 = sbias[cc + 1];
            int m1 = m0 + rr, m2 = m1 + 8;
            if (MODE == 0) {
                int b1i = m1 >> 11, nn1 = m1 & 2047;
                size_t o1 = (((size_t)(b1i * HH + hd)) * NSEQ + nn1) * DH + cc;
                uint32_t h, l;
                split2((d[0] + bb0) * sc, (d[1] + bb1) * sc, h, l);
                *(uint32_t*)&dh[o1] = h; *(uint32_t*)&dl[o1] = l;
                int b2i = m2 >> 11, nn2 = m2 & 2047;
                size_t o2 = (((size_t)(b2i * HH + hd)) * NSEQ + nn2) * DH + cc;
                split2((d[2] + bb0) * sc, (d[3] + bb1) * sc, h, l);
                *(uint32_t*)&dh[o2] = h; *(uint32_t*)&dl[o2] = l;
            } else {
                float2* p1 = (float2*)(Cout + (size_t)m1 * Nout + n0 + cc);
                *p1 = make_float2(d[0] + bb0, d[1] + bb1);
                float2* p2 = (float2*)(Cout + (size_t)m2 * Nout + n0 + cc);
                *p2 = make_float2(d[2] + bb0, d[3] + bb1);
            }
        }
    }
}

// ================= windowed flash attention — tensor core =================
// CTA: 64 q-rows, one (b,h); 256 threads = 8 warps.
#define AQ_B  272
#define AP_B  144
#define AS_W  68
#define O_QH   0
#define O_QL   17408
#define O_KV   34816
#define KV_STG 69632
#define OK_H   0
#define OK_L   17408
#define OV_H   34816
#define OV_L   52224
#define O_SF   174080
#define O_PH   191488
#define O_PL   200704
#define O_CORR 209920
#define O_LSUM 210176
#define SMEM_ATTN 210432

__global__ __launch_bounds__(256)
void attn_win()
{
    extern __shared__ char smem[];
    const uint32_t su = smem_u32(smem);
    const int tid = threadIdx.x;
    const int lane = tid & 31, wid = tid >> 5;
    const int q0 = blockIdx.x * 64;
    const int bh = blockIdx.y;
    const size_t base = (size_t)bh * NSEQ * DH;
    const float NEGINF = neg_inf();

    // ---- Q tile (hi/lo) via cp.async ----
    {
        int row = tid >> 4, ck = tid & 15;
#pragma unroll
        for (int it = 0; it < 4; it++) {
            int r = row + it * 16;
            size_t go = base + (size_t)(q0 + r) * DH + ck * 8;
            cp16(su + O_QH + r * AQ_B + ck * 16, g_qh + go);
            cp16(su + O_QL + r * AQ_B + ck * 16, g_ql + go);
        }
        asm volatile("cp.async.commit_group;" ::: "memory");
    }

    int lo = q0 - (HALFW - 1); if (lo < 0) lo = 0;
    int hi = q0 + 63 + (HALFW - 1); if (hi > NSEQ - 1) hi = NSEQ - 1;
    const int kt0 = lo & ~63;
    const int ntiles = ((hi - kt0) >> 6) + 1;

    auto load_kv = [&](int t, int s) {
        int kt = kt0 + t * 64;
        uint32_t sb = su + O_KV + s * KV_STG;
        int row = tid >> 4, ck = tid & 15;
#pragma unroll
        for (int it = 0; it < 4; it++) {
            int r = row + it * 16;
            size_t go = base + (size_t)(kt + r) * DH + ck * 8;
            uint32_t d = r * AQ_B + ck * 16;
            cp16(sb + OK_H + d, g_kh + go);
            cp16(sb + OK_L + d, g_kl + go);
            cp16(sb + OV_H + d, g_vh + go);
            cp16(sb + OV_L + d, g_vl + go);
        }
        asm volatile("cp.async.commit_group;" ::: "memory");
    };
    load_kv(0, 0);

    const int wq = wid >> 1;
    const int wk = wid & 1;
    const uint32_t aq_off = (uint32_t)(wq * 16 + (lane & 15)) * AQ_B
                          + ((lane >> 4) << 4);
    const uint32_t bk_off = (uint32_t)(wk * 32 + ((lane >> 4) << 3) + (lane & 7)) * AQ_B
                          + (((lane >> 3) & 1) << 4);
    const uint32_t ap_off = (uint32_t)(wq * 16 + (lane & 15)) * AP_B
                          + ((lane >> 4) << 4);
    const uint32_t bv_row = (lane & 7) + ((lane >> 3) & 1) * 8;
    const uint32_t bv_c16 = ((lane >> 4) << 4);

    const int tx = tid & 15, ty = tid >> 4;
    float mrow[4], lsum[4];
#pragma unroll
    for (int i = 0; i < 4; i++) { mrow[i] = NEGINF; lsum[i] = 0.0f; }

    float oacc[4][2][4];
#pragma unroll
    for (int a = 0; a < 4; a++)
#pragma unroll
        for (int b = 0; b < 2; b++)
#pragma unroll
            for (int q = 0; q < 4; q++) oacc[a][b][q] = 0.0f;

    float* Sf = (float*)(smem + O_SF);
    float* scorr = (float*)(smem + O_CORR);
    float* slsum = (float*)(smem + O_LSUM);

    for (int t = 0; t < ntiles; t++) {
        const int s = t & 1;
        const uint32_t kvb = su + O_KV + s * KV_STG;

        __syncthreads();
        if (t + 1 < ntiles) {
            load_kv(t + 1, s ^ 1);
            asm volatile("cp.async.wait_group 1;" ::: "memory");
        } else {
            asm volatile("cp.async.wait_group 0;" ::: "memory");
        }
        __syncthreads();

        // ---- phase A: S = Q K^T (3-term bf16, term-major issue) ----
        float sacc[4][4];
#pragma unroll
        for (int nt = 0; nt < 4; nt++)
#pragma unroll
            for (int q = 0; q < 4; q++) sacc[nt][q] = 0.0f;

#pragma unroll
        for (int ks = 0; ks < 8; ks++) {
            uint32_t ah[4], al[4];
            ldm4(ah, su + O_QH + aq_off + ks * 32);
            ldm4(al, su + O_QL + aq_off + ks * 32);
            uint32_t bhf[4][2], blf[4][2];
#pragma unroll
            for (int p = 0; p < 2; p++) {
                uint32_t bd = kvb + bk_off + (uint32_t)(p * 16) * AQ_B + ks * 32;
                uint32_t tt[4];
                ldm4(tt, bd + OK_H);
                bhf[2*p][0] = tt[0]; bhf[2*p][1] = tt[1];
                bhf[2*p+1][0] = tt[2]; bhf[2*p+1][1] = tt[3];
                ldm4(tt, bd + OK_L);
                blf[2*p][0] = tt[0]; blf[2*p][1] = tt[1];
                blf[2*p+1][0] = tt[2]; blf[2*p+1][1] = tt[3];
            }
#pragma unroll
            for (int term = 0; term < 3; term++) {
                const uint32_t* aa = (term == 2) ? al : ah;
#pragma unroll
                for (int nt = 0; nt < 4; nt++) {
                    const uint32_t* bb = (term == 1) ? blf[nt] : bhf[nt];
                    mma16816(sacc[nt], aa, bb[0], bb[1]);
                }
            }
        }
        {
            int r1 = wq * 16 + (lane >> 2);
            int cb = wk * 32 + (lane & 3) * 2;
#pragma unroll
            for (int nt = 0; nt < 4; nt++) {
                float* p1 = Sf + r1 * AS_W + cb + nt * 8;
                p1[0] = sacc[nt][0]; p1[1] = sacc[nt][1];
                float* p2 = p1 + 8 * AS_W;
                p2[0] = sacc[nt][2]; p2[1] = sacc[nt][3];
            }
        }
        __syncthreads();

        // ---- phase B: online softmax, P -> bf16 hi/lo planes ----
        const int kt = kt0 + t * 64;
#pragma unroll
        for (int i = 0; i < 4; i++) {
            int row = ty * 4 + i;
            int qg = q0 + row;
            float4 sv = *(float4*)(Sf + row * AS_W + tx * 4);
            float sA[4] = {sv.x, sv.y, sv.z, sv.w};
#pragma unroll
            for (int j = 0; j < 4; j++) {
                int jg = kt + tx * 4 + j;
                int d = qg - jg; if (d < 0) d = -d;
                if (d >= HALFW) sA[j] = NEGINF;
            }
            float rm = fmaxf(fmaxf(sA[0], sA[1]), fmaxf(sA[2], sA[3]));
            rm = fmaxf(rm, __shfl_xor_sync(0xffffffffu, rm, 1));
            rm = fmaxf(rm, __shfl_xor_sync(0xffffffffu, rm, 2));
            rm = fmaxf(rm, __shfl_xor_sync(0xffffffffu, rm, 4));
            rm = fmaxf(rm, __shfl_xor_sync(0xffffffffu, rm, 8));
            float mnew = fmaxf(mrow[i], rm);
            float corr, p[4];
            if (mnew == NEGINF) {
                corr = 1.0f;
                p[0] = p[1] = p[2] = p[3] = 0.0f;
            } else {
                corr = __expf(mrow[i] - mnew);
#pragma unroll
                for (int j = 0; j < 4; j++) p[j] = __expf(sA[j] - mnew);
            }
            float rs = (p[0] + p[1]) + (p[2] + p[3]);
            rs += __shfl_xor_sync(0xffffffffu, rs, 1);
            rs += __shfl_xor_sync(0xffffffffu, rs, 2);
            rs += __shfl_xor_sync(0xffffffffu, rs, 4);
            rs += __shfl_xor_sync(0xffffffffu, rs, 8);
            lsum[i] = lsum[i] * corr + rs;
            mrow[i] = mnew;
            uint32_t h01, l01, h23, l23;
            split2(p[0], p[1], h01, l01);
            split2(p[2], p[3], h23, l23);
            *(uint2*)((char*)smem + O_PH + row * AP_B + tx * 8) = make_uint2(h01, h23);
            *(uint2*)((char*)smem + O_PL + row * AP_B + tx * 8) = make_uint2(l01, l23);
            if (tx == 0) scorr[row] = corr;
        }
        __syncthreads();

        // ---- phase C: O = corr*O + P V (3-term bf16, term-major issue) ----
        {
            int r1 = wq * 16 + (lane >> 2);
            float c1 = scorr[r1], c2 = scorr[r1 + 8];
#pragma unroll
            for (int a = 0; a < 4; a++)
#pragma unroll
                for (int b = 0; b < 2; b++) {
                    oacc[a][b][0] *= c1; oacc[a][b][1] *= c1;
                    oacc[a][b][2] *= c2; oacc[a][b][3] *= c2;
                }
#pragma unroll
            for (int kk = 0; kk < 4; kk++) {
                uint32_t ph[4], pl[4];
                ldm4(ph, su + O_PH + ap_off + kk * 32);
                ldm4(pl, su + O_PL + ap_off + kk * 32);
                uint32_t vh[4][4], vl[4][4];
#pragma unroll
                for (int t16 = 0; t16 < 4; t16++) {
                    uint32_t va = kvb + (uint32_t)(kk * 16 + bv_row) * AQ_B
                                + (uint32_t)(wk * 64 + t16 * 16) * 2 + bv_c16;
                    ldm4t(vh[t16], va + OV_H);
                    ldm4t(vl[t16], va + OV_L);
                }
#pragma unroll
                for (int term = 0; term < 3; term++) {
                    const uint32_t* pp = (term == 2) ? pl : ph;
#pragma unroll
                    for (int t16 = 0; t16 < 4; t16++) {
                        const uint32_t* vv = (term == 1) ? vl[t16] : vh[t16];
                        mma16816(oacc[t16][0], pp, vv[0], vv[1]);
                        mma16816(oacc[t16][1], pp, vv[2], vv[3]);
                    }
                }
            }
        }
    }

    // ---- epilogue ----
#pragma unroll
    for (int i = 0; i < 4; i++)
        if (tx == 0) slsum[ty * 4 + i] = lsum[i];
    __syncthreads();
    {
        int r1 = wq * 16 + (lane >> 2), r2 = r1 + 8;
        float inv1 = 1.0f / slsum[r1];
        float inv2 = 1.0f / slsum[r2];
        const int b = bh >> 3, h = bh & 7;
        size_t ob1 = ((size_t)b * NSEQ + (q0 + r1)) * CDIM + h * DH;
        size_t ob2 = ((size_t)b * NSEQ + (q0 + r2)) * CDIM + h * DH;
#pragma unroll
        for (int t16 = 0; t16 < 4; t16++)
#pragma unroll
            for (int hf = 0; hf < 2; hf++) {
                int c = wk * 64 + t16 * 16 + hf * 8 + (lane & 3) * 2;
                float* d = oacc[t16][hf];
                uint32_t hh, ll;
                split2(d[0] * inv1, d[1] * inv1, hh, ll);
                *(uint32_t*)&g_atth[ob1 + c] = hh;
                *(uint32_t*)&g_attl[ob1 + c] = ll;
                split2(d[2] * inv2, d[3] * inv2, hh, ll);
                *(uint32_t*)&g_atth[ob2 + c] = hh;
                *(uint32_t*)&g_attl[ob2 + c] = ll;
            }
    }
}

// ---------------- launch ----------------
extern "C" void kernel_launch(void* const* d_in, const int* in_sizes, int n_in,
                              void* d_out, int out_size)
{
    const float* x      = (const float*)d_in[0];
    const float* w_qkv  = (const float*)d_in[1];
    const float* b_qkv  = (const float*)d_in[2];
    const float* w_proj = (const float*)d_in[3];
    const float* b_proj = (const float*)d_in[4];
    float* out = (float*)d_out;

    cudaFuncSetAttribute(gemm_bf16x3<0>,
                         cudaFuncAttributeMaxDynamicSharedMemorySize, SMEM_GEMM);
    cudaFuncSetAttribute(gemm_bf16x3<1>,
                         cudaFuncAttributeMaxDynamicSharedMemorySize, SMEM_GEMM);
    cudaFuncSetAttribute(attn_win,
                         cudaFuncAttributeMaxDynamicSharedMemorySize, SMEM_ATTN);

    // 0) split all inputs into bf16 hi/lo planes (one fused launch)
    split_all<<<(N4X + N4Q + N4P) / 256, 256>>>(x, w_qkv, w_proj);

    // 1) QKV projection -> q/k/v bf16 hi/lo planes [B,H,N,D] (q pre-scaled)
    dim3 g1((3 * CDIM) / GBN, (Bb * NSEQ) / GBM);   // (24, 16)
    gemm_bf16x3<0><<<g1, 512, SMEM_GEMM>>>(b_qkv, nullptr, CDIM, 3 * CDIM);

    // 2) banded attention (tensor core) -> g_atth/g_attl planes
    dim3 g2(NSEQ / 64, Bb * HH);                    // (32, 16)
    attn_win<<<g2, 256, SMEM_ATTN>>>();

    // 3) output projection
    dim3 g3(CDIM / GBN, (Bb * NSEQ) / GBM);         // (8, 16)
    gemm_bf16x3<1><<<g3, 512, SMEM_GEMM>>>(b_proj, out, CDIM, CDIM);
}